// round 11
// baseline (speedup 1.0000x reference)
#include <cuda_runtime.h>
#include <cuda_bf16.h>

// Problem constants (fixed by dataset: feats [8,64,32,32], N boxes)
#define B_    8
#define C_    64
#define H_    32
#define W_    32
#define HOUT  8
#define WOUT  8

#define WXP   36              // WxT row pitch (floats): 144B, 16B-aligned, bank step 4
#define OYP   36              // s_tmp oy pitch (floats)
#define CLP   296             // s_tmp channel pitch (floats): 1184B, 16B-aligned

#define NMAX  4096

#define FMA2(d, a, b, c) asm("fma.rn.f32x2 %0, %1, %2, %3;" : "=l"(d) : "l"(a), "l"(b), "l"(c))
#define PACK2(d, lo, hi) asm("mov.b64 %0, {%1, %2};" : "=l"(d) : "f"(lo), "f"(hi))
#define UNPK2(lo, hi, s) asm("mov.b64 {%0, %1}, %2;" : "=f"(lo), "=f"(hi) : "l"(s))

// Per-box precomputed weights (prep kernel -> main kernel)
__device__ unsigned long long g_Wy2[NMAX * 256];      // [n][y*8+oy], packed {w,w}
__device__ float              g_WxT[NMAX * 8 * WXP];  // [n][ox][x]
__device__ int                g_hdr[NMAX * 8];        // xc0,ncx,case,b,ylo_pack,cntmax

// ---------------------------------------------------------------------------
// Prep kernel: 4 boxes per 256-thread block; 64 threads per box.
// Computes weight matrices + per-bin-pair y-range starts + shared row count.
// ---------------------------------------------------------------------------
__global__ void prep_kernel(const int* __restrict__ batch_idxs,
                            const int* __restrict__ starts,
                            const int* __restrict__ goals, int N) {
    const int tid = threadIdx.x;
    const int bl  = tid >> 6;
    const int sub = tid & 63;
    const int n   = blockIdx.x * 4 + bl;

    __shared__ float s_Wy[4][H_ * 8];
    __shared__ float s_Wx[4][8 * WXP];

    for (int k = sub; k < H_ * 8;  k += 64) s_Wy[bl][k] = 0.0f;
    for (int k = sub; k < 8 * WXP; k += 64) s_Wx[bl][k] = 0.0f;
    __syncthreads();

    if (n < N) {
        const float sy = (float)starts[2 * n + 0];
        const float sx = (float)starts[2 * n + 1];
        const float gy = (float)goals[2 * n + 0];
        const float gx = (float)goals[2 * n + 1];
        const float y_min = fminf(sy, gy), y_max = fmaxf(sy, gy);
        const float x_min = fminf(sx, gx), x_max = fmaxf(sx, gx);

        const float start_h = y_min - 0.5f;
        const float start_w = x_min - 0.5f;
        const float bin_h = (y_max - y_min) / (float)HOUT;
        const float bin_w = (x_max - x_min) / (float)WOUT;
        const int gh = (int)ceilf(bin_h);
        const int gw = (int)ceilf(bin_w);
        const float invc = 1.0f / (float)max(gh * gw, 1);

        const int axis = sub >> 5;            // 0 = y, 1 = x
        const int idx  = sub & 31;
        const int ph   = idx >> 2;
        const int i    = idx & 3;

        const float start  = axis ? start_w : start_h;
        const float bin_sz = axis ? bin_w  : bin_h;
        const int   grid   = axis ? gw     : gh;
        const float size   = 32.0f;

        const float g_safe = fmaxf((float)grid, 1.0f);
        const float pos    = start + (float)ph * bin_sz
                           + ((float)i + 0.5f) * (bin_sz / g_safe);
        const bool  valid  = (pos >= -1.0f) && (pos <= size) && (i < grid);
        const float p      = fminf(fmaxf(pos, 0.0f), size - 1.0f);
        const float lowf   = floorf(p);
        const int   low    = (int)lowf;
        const int   high   = min(low + 1, (int)size - 1);
        const float l      = p - lowf;
        const float vf     = valid ? 1.0f : 0.0f;

        if (axis == 0) {
            atomicAdd(&s_Wy[bl][low  * 8 + ph], (1.0f - l) * vf * invc);
            atomicAdd(&s_Wy[bl][high * 8 + ph], l * vf * invc);
        } else {
            atomicAdd(&s_Wx[bl][ph * WXP + low ], (1.0f - l) * vf);
            atomicAdd(&s_Wx[bl][ph * WXP + high], l * vf);
        }

        if (sub == 0) {
            g_hdr[n * 8 + 2] = ((sy > gy) ? 2 : 0) + ((sx > gx) ? 1 : 0);
            g_hdr[n * 8 + 3] = batch_idxs[n];
        }
    }
    __syncthreads();

    if (n < N) {
        if (sub < 32) {
            // per-bin-pair y starts + shared max row count
            const int yr = sub;               // lane = y row
            int ylo[4], cnt[4], cntmax = 2;   // >=2 so s_tmp always written
            #pragma unroll
            for (int pp = 0; pp < 4; pp++) {
                const bool nz = (s_Wy[bl][yr * 8 + 2 * pp]     != 0.0f) ||
                                (s_Wy[bl][yr * 8 + 2 * pp + 1] != 0.0f);
                unsigned m = __ballot_sync(0xffffffffu, nz);
                ylo[pp] = m ? (__ffs(m) - 1) : 0;
                cnt[pp] = m ? (32 - __clz(m)) - ylo[pp] : 0;
                cntmax  = max(cntmax, cnt[pp]);
            }
            if (sub == 0) {
                unsigned ylo_pack = 0;
                #pragma unroll
                for (int pp = 0; pp < 4; pp++) {
                    const int y0c = min(ylo[pp], H_ - cntmax);  // pad rows: w==0
                    ylo_pack |= (unsigned)y0c << (pp * 8);
                }
                g_hdr[n * 8 + 4] = (int)ylo_pack;
                g_hdr[n * 8 + 5] = cntmax;
            }
        } else {
            const int lane = sub - 32;
            float s = 0.0f;
            #pragma unroll
            for (int ox = 0; ox < 8; ox++) s += s_Wx[bl][ox * WXP + lane];
            unsigned m = __ballot_sync(0xffffffffu, s != 0.0f);
            if (lane == 0) {
                if (m) {
                    const int x0  = __ffs(m) - 1;
                    const int x1  = 32 - __clz(m);          // exclusive
                    const int xc0 = x0 & ~3;
                    g_hdr[n * 8 + 0] = xc0;
                    g_hdr[n * 8 + 1] = (x1 - xc0 + 3) >> 2;
                } else { g_hdr[n * 8 + 0] = 0; g_hdr[n * 8 + 1] = 0; }
            }
        }
        for (int k = sub; k < H_ * 8; k += 64) {
            const float w = s_Wy[bl][k];
            unsigned long long pw;
            PACK2(pw, w, w);
            g_Wy2[n * 256 + k] = pw;
        }
        for (int k = sub; k < 8 * WXP; k += 64)
            g_WxT[n * 8 * WXP + k] = s_Wx[bl][k];
    }
}

// ---------------------------------------------------------------------------
// Main kernel: grid (N, 2). One weight-copy + single block barrier, then
// warp-independent passes. Pass A interleaves all 4 bin-pairs in one loop:
// 4 independent LDG.128 per iteration -> 4x the memory-level parallelism.
// ---------------------------------------------------------------------------
__global__ __launch_bounds__(256, 3)
void roi_kernel(const float* __restrict__ feats, float* __restrict__ out) {
    const int n   = blockIdx.x;
    const int h   = blockIdx.y;
    const int tid = threadIdx.x;

    __shared__ unsigned long long s_Wy2[H_ * 8];   // packed {w,w}
    __shared__ float s_WxT[8 * WXP];               // [ox][x]
    __shared__ float s_tmp[32 * CLP];              // [cl][oy][x]

#if __CUDA_ARCH__ >= 900
    cudaGridDependencySynchronize();               // PDL: wait for prep results
#endif

    // coalesced weight copy
    s_Wy2[tid] = g_Wy2[n * 256 + tid];
    if (tid < 8 * WXP)        s_WxT[tid]       = g_WxT[n * 8 * WXP + tid];
    if (tid < 8 * WXP - 256)  s_WxT[256 + tid] = g_WxT[n * 8 * WXP + 256 + tid];

    const int xc0  = __ldg(&g_hdr[n * 8 + 0]);
    const int ncx  = __ldg(&g_hdr[n * 8 + 1]);
    const int cse  = __ldg(&g_hdr[n * 8 + 2]);
    const int b    = __ldg(&g_hdr[n * 8 + 3]);
    const unsigned ylop = (unsigned)__ldg(&g_hdr[n * 8 + 4]);
    const int cm   = __ldg(&g_hdr[n * 8 + 5]);
    __syncthreads();   // the only block-wide barrier

    const int warp = tid >> 5;
    const int lane = tid & 31;

    // ---- Pass A: tmp[cl][oy][x] = sum_y Wy[y][oy] * f[c][y][x] ----
    // All 4 bin-pairs interleaved; each pair loads its own row per iteration.
    {
        const int cc = lane >> 3;             // channel within warp (0..3)
        const int xg = lane & 7;              // x group (4 floats)
        const int cl = warp * 4 + cc;
        const int c  = h * 32 + cl;

        const ulonglong2* __restrict__ fp = (const ulonglong2*)
            (feats + (size_t)(b * C_ + c) * (H_ * W_)) + xg;

        const int yl0 = (int)( ylop        & 0xFF);
        const int yl1 = (int)((ylop >> 8)  & 0xFF);
        const int yl2 = (int)((ylop >> 16) & 0xFF);
        const int yl3 = (int)((ylop >> 24) & 0xFF);

        unsigned long long acc[16];
        #pragma unroll
        for (int k = 0; k < 16; k++) acc[k] = 0ull;

        const ulonglong2* fq0 = fp + (size_t)yl0 * 8;
        const ulonglong2* fq1 = fp + (size_t)yl1 * 8;
        const ulonglong2* fq2 = fp + (size_t)yl2 * 8;
        const ulonglong2* fq3 = fp + (size_t)yl3 * 8;

        #pragma unroll 2
        for (int t = 0; t < cm; t++) {
            const ulonglong2 v0 = __ldg(fq0 + (size_t)t * 8);
            const ulonglong2 v1 = __ldg(fq1 + (size_t)t * 8);
            const ulonglong2 v2 = __ldg(fq2 + (size_t)t * 8);
            const ulonglong2 v3 = __ldg(fq3 + (size_t)t * 8);
            const ulonglong2 w0 = *(const ulonglong2*)&s_Wy2[(yl0 + t) * 8 + 0];
            const ulonglong2 w1 = *(const ulonglong2*)&s_Wy2[(yl1 + t) * 8 + 2];
            const ulonglong2 w2 = *(const ulonglong2*)&s_Wy2[(yl2 + t) * 8 + 4];
            const ulonglong2 w3 = *(const ulonglong2*)&s_Wy2[(yl3 + t) * 8 + 6];
            FMA2(acc[0],  v0.x, w0.x, acc[0]);  FMA2(acc[1],  v0.y, w0.x, acc[1]);
            FMA2(acc[2],  v0.x, w0.y, acc[2]);  FMA2(acc[3],  v0.y, w0.y, acc[3]);
            FMA2(acc[4],  v1.x, w1.x, acc[4]);  FMA2(acc[5],  v1.y, w1.x, acc[5]);
            FMA2(acc[6],  v1.x, w1.y, acc[6]);  FMA2(acc[7],  v1.y, w1.y, acc[7]);
            FMA2(acc[8],  v2.x, w2.x, acc[8]);  FMA2(acc[9],  v2.y, w2.x, acc[9]);
            FMA2(acc[10], v2.x, w2.y, acc[10]); FMA2(acc[11], v2.y, w2.y, acc[11]);
            FMA2(acc[12], v3.x, w3.x, acc[12]); FMA2(acc[13], v3.y, w3.x, acc[13]);
            FMA2(acc[14], v3.x, w3.y, acc[14]); FMA2(acc[15], v3.y, w3.y, acc[15]);
        }

        float* tp = s_tmp + cl * CLP + 4 * xg;
        #pragma unroll
        for (int oy = 0; oy < 8; oy++) {
            ulonglong2 r;
            r.x = acc[2 * oy];
            r.y = acc[2 * oy + 1];
            *reinterpret_cast<ulonglong2*>(tp + oy * OYP) = r;
        }
    }
    __syncwarp();      // warp-local: pass B reads only this warp's tmp region

    // ---- Pass B: out[c][bin] = sum_x Wx[x][ox_s] * tmp[cl][oy_s][x] ----
    {
        #pragma unroll
        for (int half = 0; half < 2; half++) {
            const int bin = half * 32 + lane;
            const int py  = bin >> 3;
            const int px  = bin & 7;
            int oy_s, ox_s;                    // source bin after flip
            if      (cse == 0) { oy_s = py;     ox_s = px;     }
            else if (cse == 3) { oy_s = 7 - py; ox_s = px;     }
            else               { oy_s = py;     ox_s = 7 - py; }

            unsigned long long a2[4];
            #pragma unroll
            for (int ch = 0; ch < 4; ch++) a2[ch] = 0ull;

            const float* wrow = s_WxT + ox_s * WXP;
            const float* trow = s_tmp + (warp * 4) * CLP + oy_s * OYP;

            for (int k = 0; k < ncx; k++) {
                const int x4 = xc0 + 4 * k;
                const ulonglong2 wv = *reinterpret_cast<const ulonglong2*>(wrow + x4);
                #pragma unroll
                for (int ch = 0; ch < 4; ch++) {
                    const ulonglong2 tv =
                        *reinterpret_cast<const ulonglong2*>(trow + ch * CLP + x4);
                    FMA2(a2[ch], tv.x, wv.x, a2[ch]);
                    FMA2(a2[ch], tv.y, wv.y, a2[ch]);
                }
            }

            float* __restrict__ ob =
                out + (size_t)n * (C_ * HOUT * WOUT)
                    + (size_t)(h * 32 + warp * 4) * 64 + bin;
            #pragma unroll
            for (int ch = 0; ch < 4; ch++) {
                float lo, hi;
                UNPK2(lo, hi, a2[ch]);
                ob[(size_t)ch * 64] = lo + hi;     // 128B coalesced per (half,ch)
            }
        }
    }
}

extern "C" void kernel_launch(void* const* d_in, const int* in_sizes, int n_in,
                              void* d_out, int out_size) {
    const float* feats      = (const float*)d_in[0];
    const int*   batch_idxs = (const int*)d_in[1];
    const int*   starts     = (const int*)d_in[2];
    const int*   goals      = (const int*)d_in[3];
    float*       out        = (float*)d_out;

    const int N = in_sizes[1];   // number of boxes (1024)

    prep_kernel<<<(N + 3) / 4, 256>>>(batch_idxs, starts, goals, N);

    // roi kernel launched with PDL so its blocks spin up while prep drains;
    // cudaGridDependencySynchronize() in-kernel guards the data dependency.
    cudaLaunchConfig_t cfg = {};
    cfg.gridDim  = dim3((unsigned)N, 2, 1);
    cfg.blockDim = dim3(256, 1, 1);
    cfg.dynamicSmemBytes = 0;
    cudaLaunchAttribute attr[1];
    attr[0].id = cudaLaunchAttributeProgrammaticStreamSerialization;
    attr[0].val.programmaticStreamSerializationAllowed = 1;
    cfg.attrs = attr;
    cfg.numAttrs = 1;
    cudaLaunchKernelEx(&cfg, roi_kernel, feats, out);
}